// round 1
// baseline (speedup 1.0000x reference)
#include <cuda_runtime.h>
#include <cuda_bf16.h>
#include <cstdint>

#define BB 8
#define QQ 100
#define TTD 50
#define HW 65536
#define MPAD 128
#define NPAD 64
#define KC 64
#define LDE 72            // smem row stride in elements (KC + 8 pad -> conflict-free ldmatrix)
#define SPLITS 64
#define HWB (HW / SPLITS) // 1024
#define NCHUNK (HWB / KC) // 16

// Scratch (statically allocated; zeroed each launch via captured memset nodes)
__device__ float g_DX[BB * MPAD * NPAD];
__device__ float g_DS[BB * MPAD * NPAD];
__device__ float g_SN[BB * MPAD];

__device__ __forceinline__ uint32_t smem_u32(const void* p) {
    return (uint32_t)__cvta_generic_to_shared(p);
}

__global__ __launch_bounds__(256, 2)
void cost_main_kernel(const float* __restrict__ pred, const int* __restrict__ tgt) {
    __shared__ __align__(16) __nv_bfloat16 sX[MPAD * LDE];
    __shared__ __align__(16) __nv_bfloat16 sS[MPAD * LDE];
    __shared__ __align__(16) __nv_bfloat16 sT[NPAD * LDE];

    const int tid   = threadIdx.x;
    const int b     = blockIdx.x >> 6;
    const int split = blockIdx.x & 63;
    const int lane  = tid & 31;
    const int warp  = tid >> 5;

    // Zero all smem once; pad rows (q>=100, t>=50) stay zero for the whole kernel.
    for (int i = tid; i < MPAD * LDE; i += 256) {
        sX[i] = __float2bfloat16(0.f);
        sS[i] = __float2bfloat16(0.f);
    }
    for (int i = tid; i < NPAD * LDE; i += 256) sT[i] = __float2bfloat16(0.f);
    __syncthreads();
    // Ones rows: S row 100 (-> column sums of T = sumT), T row 50 (-> row sums of S = sumS)
    for (int i = tid; i < KC; i += 256) {
        sS[100 * LDE + i] = __float2bfloat16(1.f);
        sT[50  * LDE + i] = __float2bfloat16(1.f);
    }

    // Accumulators: warp w owns m-tile w (rows 16w..16w+15), all 8 n-tiles.
    float accX[8][4], accS[8][4];
    #pragma unroll
    for (int i = 0; i < 8; i++)
        #pragma unroll
        for (int j = 0; j < 4; j++) { accX[i][j] = 0.f; accS[i][j] = 0.f; }
    float accSP = 0.f;

    // ldmatrix source addresses (bytes). A: row = warp*16 + lane%16, col = (lane/16)*8.
    const uint32_t a_off = ((uint32_t)(warp * 16 + (lane & 15)) * LDE + ((lane >> 4) << 3)) * 2u;
    const uint32_t xlm = smem_u32(sX) + a_off;
    const uint32_t slm = smem_u32(sS) + a_off;
    // B (x4 covers n-tiles 2p,2p+1): row = p*16 + lane%8 + ((lane>=16)?8:0), col = ((lane>>3)&1)*8
    uint32_t tlm[4];
    #pragma unroll
    for (int p = 0; p < 4; p++) {
        uint32_t row = (uint32_t)(p * 16 + (lane & 7) + (((lane >> 4) & 1) << 3));
        uint32_t col = ((lane >> 3) & 1) << 3;
        tlm[p] = smem_u32(sT) + (row * LDE + col) * 2u;
    }

    const int r  = tid >> 1;   // q row for x-loader threads
    const int hf = tid & 1;    // which 32-element half of the 64-wide chunk
    const float4* px = nullptr;
    if (tid < 200)
        px = reinterpret_cast<const float4*>(
            pred + (size_t)(b * QQ + r) * HW + (size_t)split * HWB + hf * 32);

    for (int ch = 0; ch < NCHUNK; ch++) {
        const int cofs = ch * KC;
        __syncthreads();   // previous chunk's mma done reading smem

        if (tid < 200) {
            // x path: 32 floats -> sigmoid + softplus + bf16 stores
            const float4* p4 = px + (cofs >> 2);
            __nv_bfloat162* dx = reinterpret_cast<__nv_bfloat162*>(&sX[r * LDE + hf * 32]);
            __nv_bfloat162* ds = reinterpret_cast<__nv_bfloat162*>(&sS[r * LDE + hf * 32]);
            #pragma unroll
            for (int i = 0; i < 8; i++) {
                float4 v = p4[i];
                float xs[4] = { v.x, v.y, v.z, v.w };
                float sg[4];
                #pragma unroll
                for (int j = 0; j < 4; j++) {
                    float x   = xs[j];
                    float e   = __expf(-fabsf(x));             // MUFU ex2 (e in (0,1])
                    float inv = __fdividef(1.f, 1.f + e);      // MUFU rcp
                    sg[j] = (x >= 0.f) ? inv : e * inv;        // sigmoid, overflow-safe
                    accSP += fmaxf(x, 0.f) + __logf(1.f + e);  // softplus, MUFU lg2
                }
                dx[i * 2]     = __floats2bfloat162_rn(xs[0], xs[1]);
                dx[i * 2 + 1] = __floats2bfloat162_rn(xs[2], xs[3]);
                ds[i * 2]     = __floats2bfloat162_rn(sg[0], sg[1]);
                ds[i * 2 + 1] = __floats2bfloat162_rn(sg[2], sg[3]);
            }
        } else {
            // t path: 100 slots (50 rows x 2 halves) over 56 threads
            for (int slot = tid - 200; slot < 100; slot += 56) {
                int tr = slot >> 1, th = slot & 1;
                const int4* p4 = reinterpret_cast<const int4*>(
                    tgt + (size_t)(b * TTD + tr) * HW + (size_t)split * HWB + cofs + th * 32);
                __nv_bfloat162* dt = reinterpret_cast<__nv_bfloat162*>(&sT[tr * LDE + th * 32]);
                #pragma unroll
                for (int i = 0; i < 8; i++) {
                    int4 v = p4[i];
                    dt[i * 2]     = __floats2bfloat162_rn((float)v.x, (float)v.y);
                    dt[i * 2 + 1] = __floats2bfloat162_rn((float)v.z, (float)v.w);
                }
            }
        }
        __syncthreads();

        // 128x64 double GEMM over KC=64 (4 k-steps of 16)
        #pragma unroll
        for (int ks = 0; ks < 4; ks++) {
            uint32_t a0, a1, a2, a3, s0, s1, s2, s3;
            asm volatile("ldmatrix.sync.aligned.m8n8.x4.shared.b16 {%0,%1,%2,%3}, [%4];\n"
                : "=r"(a0), "=r"(a1), "=r"(a2), "=r"(a3) : "r"(xlm + ks * 32));
            asm volatile("ldmatrix.sync.aligned.m8n8.x4.shared.b16 {%0,%1,%2,%3}, [%4];\n"
                : "=r"(s0), "=r"(s1), "=r"(s2), "=r"(s3) : "r"(slm + ks * 32));
            #pragma unroll
            for (int p = 0; p < 4; p++) {
                uint32_t b0, b1, b2, b3;
                asm volatile("ldmatrix.sync.aligned.m8n8.x4.shared.b16 {%0,%1,%2,%3}, [%4];\n"
                    : "=r"(b0), "=r"(b1), "=r"(b2), "=r"(b3) : "r"(tlm[p] + ks * 32));
                asm volatile("mma.sync.aligned.m16n8k16.row.col.f32.bf16.bf16.f32 "
                    "{%0,%1,%2,%3},{%4,%5,%6,%7},{%8,%9},{%0,%1,%2,%3};\n"
                    : "+f"(accX[2*p][0]), "+f"(accX[2*p][1]), "+f"(accX[2*p][2]), "+f"(accX[2*p][3])
                    : "r"(a0), "r"(a1), "r"(a2), "r"(a3), "r"(b0), "r"(b1));
                asm volatile("mma.sync.aligned.m16n8k16.row.col.f32.bf16.bf16.f32 "
                    "{%0,%1,%2,%3},{%4,%5,%6,%7},{%8,%9},{%0,%1,%2,%3};\n"
                    : "+f"(accX[2*p+1][0]), "+f"(accX[2*p+1][1]), "+f"(accX[2*p+1][2]), "+f"(accX[2*p+1][3])
                    : "r"(a0), "r"(a1), "r"(a2), "r"(a3), "r"(b2), "r"(b3));
                asm volatile("mma.sync.aligned.m16n8k16.row.col.f32.bf16.bf16.f32 "
                    "{%0,%1,%2,%3},{%4,%5,%6,%7},{%8,%9},{%0,%1,%2,%3};\n"
                    : "+f"(accS[2*p][0]), "+f"(accS[2*p][1]), "+f"(accS[2*p][2]), "+f"(accS[2*p][3])
                    : "r"(s0), "r"(s1), "r"(s2), "r"(s3), "r"(b0), "r"(b1));
                asm volatile("mma.sync.aligned.m16n8k16.row.col.f32.bf16.bf16.f32 "
                    "{%0,%1,%2,%3},{%4,%5,%6,%7},{%8,%9},{%0,%1,%2,%3};\n"
                    : "+f"(accS[2*p+1][0]), "+f"(accS[2*p+1][1]), "+f"(accS[2*p+1][2]), "+f"(accS[2*p+1][3])
                    : "r"(s0), "r"(s1), "r"(s2), "r"(s3), "r"(b2), "r"(b3));
            }
        }
    }

    // Epilogue: accumulate partial dot-products into global scratch (REDG adds).
    const int mrow = warp * 16 + (lane >> 2);
    const int ncol = (lane & 3) * 2;
    float* dxb = g_DX + b * MPAD * NPAD;
    float* dsb = g_DS + b * MPAD * NPAD;
    #pragma unroll
    for (int nt = 0; nt < 8; nt++) {
        int c0i = mrow * NPAD + nt * 8 + ncol;
        int c1i = c0i + 8 * NPAD;
        atomicAdd(dxb + c0i,     accX[nt][0]);
        atomicAdd(dxb + c0i + 1, accX[nt][1]);
        atomicAdd(dxb + c1i,     accX[nt][2]);
        atomicAdd(dxb + c1i + 1, accX[nt][3]);
        atomicAdd(dsb + c0i,     accS[nt][0]);
        atomicAdd(dsb + c0i + 1, accS[nt][1]);
        atomicAdd(dsb + c1i,     accS[nt][2]);
        atomicAdd(dsb + c1i + 1, accS[nt][3]);
    }
    // softplus row sums: combine the two threads sharing a q-row, one atomic per row.
    float tot = accSP + __shfl_xor_sync(0xffffffffu, accSP, 1);
    if (tid < 200 && (tid & 1) == 0)
        atomicAdd(&g_SN[b * MPAD + r], tot);
}

__global__ void finalize_kernel(float* __restrict__ out) {
    int idx = blockIdx.x * blockDim.x + threadIdx.x;
    if (idx >= BB * QQ * TTD) return;
    int b   = idx / (QQ * TTD);
    int rem = idx % (QQ * TTD);
    int q   = rem / TTD;
    int t   = rem % TTD;

    const float dX   = g_DX[(b * MPAD + q) * NPAD + t];
    const float dS   = g_DS[(b * MPAD + q) * NPAD + t];
    const float sumS = g_DS[(b * MPAD + q) * NPAD + 50];    // ones T-row
    const float sumT = g_DS[(b * MPAD + 100) * NPAD + t];   // ones S-row
    const float sn   = g_SN[b * MPAD + q];

    float ce   = (sn - dX) * (1.f / (float)HW);
    float dice = 1.f - (2.f * dS + 1.f) / (sumS + sumT + 1.f);
    out[idx] = ce + dice;
}

extern "C" void kernel_launch(void* const* d_in, const int* in_sizes, int n_in,
                              void* d_out, int out_size) {
    const float* pred = (const float*)d_in[0];
    const int*   tgt  = (const int*)d_in[1];
    float*       out  = (float*)d_out;

    void* p;
    cudaGetSymbolAddress(&p, g_DX); cudaMemsetAsync(p, 0, sizeof(float) * BB * MPAD * NPAD);
    cudaGetSymbolAddress(&p, g_DS); cudaMemsetAsync(p, 0, sizeof(float) * BB * MPAD * NPAD);
    cudaGetSymbolAddress(&p, g_SN); cudaMemsetAsync(p, 0, sizeof(float) * BB * MPAD);

    cost_main_kernel<<<BB * SPLITS, 256>>>(pred, tgt);
    finalize_kernel<<<(BB * QQ * TTD + 255) / 256, 256>>>(out);
}